// round 1
// baseline (speedup 1.0000x reference)
#include <cuda_runtime.h>

// Problem constants
#define BB 4096
#define TT 400
#define CC 42
#define HH 16

// Scratch: U[bblk(256)][t(400)][ploc(8)][i(16)] as f32x2 pairs (batch-pair interleaved)
// 256*400*8*16 u64 = 13,107,200 * 8B = 104.9 MB
__device__ __align__(16) unsigned long long g_U[256ull * 400 * 8 * 16];

// ---------- f32x2 helpers ----------
__device__ __forceinline__ unsigned long long pk2(float lo, float hi) {
    unsigned long long r;
    asm("mov.b64 %0, {%1, %2};" : "=l"(r) : "f"(lo), "f"(hi));
    return r;
}
__device__ __forceinline__ void up2(unsigned long long v, float& a, float& b) {
    asm("mov.b64 {%0, %1}, %2;" : "=f"(a), "=f"(b) : "l"(v));
}
__device__ __forceinline__ unsigned long long fma2(unsigned long long a, unsigned long long b,
                                                   unsigned long long c) {
    unsigned long long d;
    asm("fma.rn.f32x2 %0, %1, %2, %3;" : "=l"(d) : "l"(a), "l"(b), "l"(c));
    return d;
}
__device__ __forceinline__ unsigned long long add2(unsigned long long a, unsigned long long b) {
    unsigned long long d;
    asm("add.rn.f32x2 %0, %1, %2;" : "=l"(d) : "l"(a), "l"(b));
    return d;
}
// tanh(x) = 1 - 2/(1+e^{2x}); ex2/rcp approx => ~1e-7 rel err, saturates correctly at +-inf
__device__ __forceinline__ float tanh_f(float x) {
    float e, r;
    asm("ex2.approx.f32 %0, %1;" : "=f"(e) : "f"(x * 2.8853900817779268f));
    asm("rcp.approx.f32 %0, %1;" : "=f"(r) : "f"(e + 1.0f));
    return fmaf(-2.0f, r, 1.0f);
}
__device__ __forceinline__ unsigned long long tanh2(unsigned long long v) {
    float a, b;
    up2(v, a, b);
    return pk2(tanh_f(a), tanh_f(b));
}

// ---------- Kernel A: input projection U[t] = bias0 + W_ih0 @ x_t (all b, t) ----------
// warp = 2 batch-pairs x 16 timesteps. Lane (s = l>>4 picks pair, tl = l&15 picks t).
// x loads coalesced along t (64B runs). Each lane computes 16 hidden outputs for both
// batches of its pair as f32x2, writes 128B contiguous into g_U.
__global__ void __launch_bounds__(128) kA(const float* __restrict__ x,
                                          const float* __restrict__ Wih0,
                                          const float* __restrict__ bih0,
                                          const float* __restrict__ bhh0) {
    __shared__ __align__(16) unsigned long long swd[CC][HH];  // duplicated weight pairs [c][i]
    __shared__ unsigned long long sbias[HH];

    int tid = threadIdx.x;
    for (int k = tid; k < CC * HH; k += 128) {
        int c = k / HH, i = k % HH;
        float w = Wih0[i * CC + c];
        swd[c][i] = pk2(w, w);
    }
    if (tid < HH) {
        float bs = bih0[tid] + bhh0[tid];
        sbias[tid] = pk2(bs, bs);
    }
    __syncthreads();

    int wl = blockIdx.x * 4 + (tid >> 5);  // 25600 warps total
    int lane = tid & 31;
    int s = lane >> 4, tl = lane & 15;
    int tchunk = wl % 25;
    int pp = wl / 25;          // 0..1023
    int p = pp * 2 + s;        // batch pair index 0..2047
    int t = tchunk * 16 + tl;  // 0..399

    const float* xb0 = x + (size_t)(2 * p) * (CC * TT) + t;
    const float* xb1 = xb0 + (CC * TT);

    unsigned long long u[16];
#pragma unroll
    for (int i = 0; i < 16; i++) u[i] = sbias[i];

#pragma unroll 7
    for (int c = 0; c < CC; c++) {
        float xa = xb0[c * TT];
        float xb = xb1[c * TT];
        unsigned long long xp = pk2(xa, xb);
        const ulonglong2* wp = (const ulonglong2*)&swd[c][0];
#pragma unroll
        for (int k = 0; k < 8; k++) {
            ulonglong2 w2 = wp[k];
            u[2 * k]     = fma2(w2.x, xp, u[2 * k]);
            u[2 * k + 1] = fma2(w2.y, xp, u[2 * k + 1]);
        }
    }

    unsigned long long* dst = g_U + ((size_t)(p >> 3) * TT + t) * 128 + (size_t)(p & 7) * 16;
    ulonglong2* d2 = (ulonglong2*)dst;
#pragma unroll
    for (int k = 0; k < 8; k++) d2[k] = make_ulonglong2(u[2 * k], u[2 * k + 1]);
}

// ---------- Kernel B: fused 2-layer recurrence + final FC ----------
// warp = 16 hidden lanes x 2 pair-slots (4 batches). Block = 4 warps = 16 batches.
// Weight rows register-resident as duplicated f32x2. h exchange via smem + __syncwarp.
__global__ void __launch_bounds__(128, 2) kB(const float* __restrict__ h0in,
                                             const float* __restrict__ Whh0,
                                             const float* __restrict__ Wih1,
                                             const float* __restrict__ Whh1,
                                             const float* __restrict__ bih1,
                                             const float* __restrict__ bhh1,
                                             const float* __restrict__ Wfc,
                                             const float* __restrict__ bfc,
                                             float* __restrict__ out) {
    __shared__ __align__(16) unsigned long long hx0[4][2][16];
    __shared__ __align__(16) unsigned long long hx1[4][2][16];

    int tid = threadIdx.x;
    int w = tid >> 5;
    int lane = tid & 31;
    int s = lane >> 4;
    int i = lane & 15;
    int ploc = w * 2 + s;          // 0..7
    int bblk = blockIdx.x;         // 0..255
    int p = bblk * 8 + ploc;       // pair 0..2047
    int b0 = 2 * p, b1 = b0 + 1;

    // register-resident duplicated weight rows
    unsigned long long wh0[16], wi1[16], wh1[16];
#pragma unroll
    for (int j = 0; j < 16; j++) {
        float v0 = Whh0[i * 16 + j];
        float v1 = Wih1[i * 16 + j];
        float v2 = Whh1[i * 16 + j];
        wh0[j] = pk2(v0, v0);
        wi1[j] = pk2(v1, v1);
        wh1[j] = pk2(v2, v2);
    }
    float bb = bih1[i] + bhh1[i];
    const unsigned long long bias1 = pk2(bb, bb);

    // initial hidden state (broadcast loads; h0 layout (2, B, H))
    unsigned long long h0a[16], h1a[16];
#pragma unroll
    for (int j = 0; j < 16; j++) {
        h0a[j] = pk2(h0in[b0 * 16 + j], h0in[b1 * 16 + j]);
        h1a[j] = pk2(h0in[BB * HH + b0 * 16 + j], h0in[BB * HH + b1 * 16 + j]);
    }

    // U stream pointers (per-lane element: [bblk][t][ploc][i], stride 128 per t)
    const unsigned long long* up = g_U + (size_t)bblk * TT * 128 + (size_t)ploc * 16 + i;
    unsigned long long ub[4];
#pragma unroll
    for (int k = 0; k < 4; k++) ub[k] = up[(size_t)k * 128];
    const unsigned long long* upf = up + 4 * 128;
    const unsigned long long* upmax = up + (size_t)(TT - 1) * 128;

    unsigned long long* myh0 = &hx0[w][s][i];
    unsigned long long* myh1 = &hx1[w][s][i];
    const ulonglong2* rd0 = (const ulonglong2*)&hx0[w][s][0];
    const ulonglong2* rd1 = (const ulonglong2*)&hx1[w][s][0];

    const unsigned long long ZERO = 0ull;

    for (int t = 0; t < TT; t += 4) {
#pragma unroll
        for (int j = 0; j < 4; j++) {
            unsigned long long u0 = ub[j];
            // prefetch t+j+4 (clamped)
            const unsigned long long* pf = (upf <= upmax) ? upf : upmax;
            ub[j] = *pf;
            upf += 128;

            // layer0 recurrence (2 accumulator chains)
            unsigned long long a0 = u0, a1 = ZERO;
#pragma unroll
            for (int jj = 0; jj < 16; jj += 2) {
                a0 = fma2(wh0[jj], h0a[jj], a0);
                a1 = fma2(wh0[jj + 1], h0a[jj + 1], a1);
            }
            unsigned long long h0n = tanh2(add2(a0, a1));

            // layer1 recurrent part (independent of h0n -> overlaps tanh latency)
            unsigned long long c0 = bias1, c1 = ZERO;
#pragma unroll
            for (int jj = 0; jj < 16; jj += 2) {
                c0 = fma2(wh1[jj], h1a[jj], c0);
                c1 = fma2(wh1[jj + 1], h1a[jj + 1], c1);
            }

            // exchange h0
            *myh0 = h0n;
            __syncwarp();
#pragma unroll
            for (int k = 0; k < 8; k++) {
                ulonglong2 v = rd0[k];
                h0a[2 * k] = v.x;
                h0a[2 * k + 1] = v.y;
            }

            // layer1 input part
#pragma unroll
            for (int jj = 0; jj < 16; jj += 2) {
                c0 = fma2(wi1[jj], h0a[jj], c0);
                c1 = fma2(wi1[jj + 1], h0a[jj + 1], c1);
            }
            unsigned long long h1n = tanh2(add2(c0, c1));

            // exchange h1
            *myh1 = h1n;
            __syncwarp();
#pragma unroll
            for (int k = 0; k < 8; k++) {
                ulonglong2 v = rd1[k];
                h1a[2 * k] = v.x;
                h1a[2 * k + 1] = v.y;
            }
        }
    }

    // final FC: out[b][c] = sum_i h1[b][i] * Wfc[c][i] + bfc[c]   (NC = 2)
    if (i < 2) {
        float bf = bfc[i];
        unsigned long long acc = pk2(bf, bf);
#pragma unroll
        for (int j = 0; j < 16; j++) {
            float wv = Wfc[i * 16 + j];
            acc = fma2(pk2(wv, wv), h1a[j], acc);
        }
        float oa, ob;
        up2(acc, oa, ob);
        out[b0 * 2 + i] = oa;
        out[b1 * 2 + i] = ob;
    }
}

extern "C" void kernel_launch(void* const* d_in, const int* in_sizes, int n_in,
                              void* d_out, int out_size) {
    const float* x    = (const float*)d_in[0];
    const float* h0   = (const float*)d_in[1];
    const float* Wih0 = (const float*)d_in[2];
    const float* Whh0 = (const float*)d_in[3];
    const float* bih0 = (const float*)d_in[4];
    const float* bhh0 = (const float*)d_in[5];
    const float* Wih1 = (const float*)d_in[6];
    const float* Whh1 = (const float*)d_in[7];
    const float* bih1 = (const float*)d_in[8];
    const float* bhh1 = (const float*)d_in[9];
    const float* Wfc  = (const float*)d_in[10];
    const float* bfc  = (const float*)d_in[11];
    float* out = (float*)d_out;

    // A: 25600 warps -> 6400 blocks of 128
    kA<<<6400, 128>>>(x, Wih0, bih0, bhh0);
    // B: 1024 warps -> 256 blocks of 128 (16 batches per block)
    kB<<<256, 128>>>(h0, Whh0, Wih1, Whh1, bih1, bhh1, Wfc, bfc, out);
}